// round 7
// baseline (speedup 1.0000x reference)
#include <cuda_runtime.h>
#include <cuda_fp16.h>
#include <cuda.h>
#include <math.h>
#include <stdint.h>

// DelayAndSumLinear, round 6.
// R5 was latency-bound on the 64MB LUT DRAM stream (LDG long-scoreboard;
// nothing >67% in the roofline). Changes:
//  - LUT stream moved to TMA: 2D box [8 floats x 256 pixels] (32B per pixel,
//    1024B pixel stride), double-buffered in smem, mbarrier-paced. No more
//    warp-visible DRAM latency; L2 promotion NONE keeps DRAM at 32B sectors.
//  - 1 thread = 1 pixel (all 4 dets): LUT read = 2 coalesced LDS.128,
//    no shfl, atomics warp-coalesced (1 wf per b).
//  - 512 thr, 96KB smem, 2 blocks/SM, grid 288 (9x32) = one clean wave.

#define NT      2048
#define NDET    128
#define NPIX    65536
#define NB      4
#define DCH     4
#define GRIDY   (NDET / DCH)         // 32
#define PTILES  9                    // 9*32 = 288 blocks = 1 wave @ 2/SM
#define THREADS 512
#define PPP     512                  // pixels per stage (2 TMA boxes of 256)
#define SMEM_ENTRIES (DCH * NT)      // sino: 8192 x uint2 = 64 KB

#define SINO_BYTES   (SMEM_ENTRIES * 8)          // 65536
#define LUTBUF_BYTES (PPP * 32)                  // 16384 per buffer
#define OFF_LUT0     SINO_BYTES                  // 65536
#define OFF_LUT1     (OFF_LUT0 + LUTBUF_BYTES)   // 81920
#define OFF_MBAR     (OFF_LUT1 + LUTBUF_BYTES)   // 98304
#define SMEM_TOTAL   (OFF_MBAR + 64)

__device__ __forceinline__ uint32_t smem_u32(const void* p) {
    uint32_t a;
    asm("{ .reg .u64 t; cvta.to.shared.u64 t, %1; cvt.u32.u64 %0, t; }"
        : "=r"(a) : "l"(p));
    return a;
}
__device__ __forceinline__ void mbar_init(uint32_t m, uint32_t cnt) {
    asm volatile("mbarrier.init.shared.b64 [%0], %1;" :: "r"(m), "r"(cnt) : "memory");
}
__device__ __forceinline__ void mbar_expect(uint32_t m, uint32_t bytes) {
    asm volatile("mbarrier.arrive.expect_tx.shared.b64 _, [%0], %1;"
                 :: "r"(m), "r"(bytes) : "memory");
}
__device__ __forceinline__ void mbar_wait(uint32_t m, uint32_t parity) {
    asm volatile(
        "{\n\t.reg .pred P;\n\t"
        "W%=:\n\t"
        "mbarrier.try_wait.parity.acquire.cta.shared::cta.b64 P, [%0], %1, 0x989680;\n\t"
        "@P bra D%=;\n\t"
        "bra W%=;\n\t"
        "D%=:\n\t}"
        :: "r"(m), "r"(parity) : "memory");
}
__device__ __forceinline__ void tma_2d(uint32_t dst, const CUtensorMap* map,
                                       int x, int y, uint32_t mbar) {
    asm volatile(
        "cp.async.bulk.tensor.2d.shared::cta.global.tile.mbarrier::complete_tx::bytes "
        "[%0], [%1, {%2, %3}], [%4];"
        :: "r"(dst), "l"(map), "r"(x), "r"(y), "r"(mbar) : "memory");
}

__global__ __launch_bounds__(THREADS, 2)
void das_kernel(const __grid_constant__ CUtensorMap tmap,
                const float* __restrict__ sino,
                float* __restrict__ out)
{
    extern __shared__ char smem[];
    uint2* s2 = (uint2*)smem;                       // sino chunk
    const uint32_t sbase = smem_u32(smem);
    const uint32_t mbar0 = sbase + OFF_MBAR;
    const uint32_t mbar1 = sbase + OFF_MBAR + 8;

    const int tid   = threadIdx.x;
    const int dbase = blockIdx.y * DCH;
    const int xcoord = dbase * 2;                   // LUT dim0 element offset

    const int tileSize = (NPIX + PTILES - 1) / PTILES;  // 7282
    const int p0 = blockIdx.x * tileSize;
    const int p1 = min(p0 + tileSize, NPIX);
    const int span  = p1 - p0;
    const int nPass = (span + PPP - 1) / PPP;           // 15

    // ---- init mbarriers, then kick off stage 0's TMA (overlaps the fill) ----
    if (tid == 0) { mbar_init(mbar0, 1); mbar_init(mbar1, 1); }
    __syncthreads();
    if (tid == 0) {
        mbar_expect(mbar0, 2 * 256 * 32);
        tma_2d(sbase + OFF_LUT0,       &tmap, xcoord, p0,       mbar0);
        tma_2d(sbase + OFF_LUT0 + 8192, &tmap, xcoord, p0 + 256, mbar0);
    }

    // ---- stage sino chunk: 4 dets x 2048 t x 4 batches as fp16 quads ----
    #pragma unroll
    for (int it = 0; it < SMEM_ENTRIES / THREADS; ++it) {
        int idx = it * THREADS + tid;
        int j   = idx >> 11;
        int t   = idx & (NT - 1);
        const float* sp = sino + (size_t)(dbase + j) * NT + t;
        float f0 = sp[0 * NDET * NT];
        float f1 = sp[1 * NDET * NT];
        float f2 = sp[2 * NDET * NT];
        float f3 = sp[3 * NDET * NT];
        half2 h01 = __floats2half2_rn(f0, f1);
        half2 h23 = __floats2half2_rn(f2, f3);
        uint2 v;
        v.x = *(unsigned*)&h01;
        v.y = *(unsigned*)&h23;
        s2[idx] = v;
    }

    // Hann apodization / norm folded per det (Hann sum over 128 pts = 63.5).
    float w[DCH];
    #pragma unroll
    for (int j = 0; j < DCH; ++j) {
        float d = (float)(dbase + j);
        w[j] = (0.5f - 0.5f * cosf(6.283185307179586f * d / 127.0f))
               * (1.0f / 63.5f);
    }

    __syncthreads();   // sino chunk ready (also orders mbar inits block-wide)

    for (int i = 0; i < nPass; ++i) {
        const int      buf  = i & 1;
        const uint32_t mbar = buf ? mbar1 : mbar0;

        // issue stage i+1 into the other buffer (its last reader was stage
        // i-1, already synced)
        if (i + 1 < nPass && tid == 0) {
            uint32_t nb   = sbase + (((i + 1) & 1) ? OFF_LUT1 : OFF_LUT0);
            uint32_t nm   = ((i + 1) & 1) ? mbar1 : mbar0;
            int      ybase = p0 + (i + 1) * PPP;
            mbar_expect(nm, 2 * 256 * 32);
            tma_2d(nb,        &tmap, xcoord, ybase,       nm);
            tma_2d(nb + 8192, &tmap, xcoord, ybase + 256, nm);
        }

        mbar_wait(mbar, (i >> 1) & 1);

        int p = p0 + i * PPP + tid;
        if (p < p1) {
            const float4* lb = (const float4*)(smem + (buf ? OFF_LUT1 : OFF_LUT0));
            float4 A = lb[tid * 2];       // (tof0,a0,tof1,a1)
            float4 B = lb[tid * 2 + 1];   // (tof2,a2,tof3,a3)

            float tofs[DCH] = {A.x, A.z, B.x, B.z};
            float als [DCH] = {A.y, A.w, B.y, B.w};

            float acc0 = 0.f, acc1 = 0.f, acc2 = 0.f, acc3 = 0.f;
            #pragma unroll
            for (int j = 0; j < DCH; ++j) {
                float tof = tofs[j];
                float al  = als[j];
                float kf  = floorf(tof);
                int   k0  = (int)fminf(fmaxf(kf, 0.0f), (float)(NT - 2));
                float wv  = (kf >= 0.0f && kf <= (float)(NT - 2)) ? w[j] : 0.0f;

                uint2 e0 = s2[j * NT + k0];
                uint2 e1 = s2[j * NT + k0 + 1];
                float2 s0a = __half22float2(*(half2*)&e0.x);
                float2 s0b = __half22float2(*(half2*)&e0.y);
                float2 s1a = __half22float2(*(half2*)&e1.x);
                float2 s1b = __half22float2(*(half2*)&e1.y);

                float wa = wv * al;
                float wb = wv - wa;
                acc0 = fmaf(wb, s0a.x, fmaf(wa, s1a.x, acc0));
                acc1 = fmaf(wb, s0a.y, fmaf(wa, s1a.y, acc1));
                acc2 = fmaf(wb, s0b.x, fmaf(wa, s1b.x, acc2));
                acc3 = fmaf(wb, s0b.y, fmaf(wa, s1b.y, acc3));
            }

            atomicAdd(&out[0 * NPIX + p], acc0);   // warp-coalesced REDG
            atomicAdd(&out[1 * NPIX + p], acc1);
            atomicAdd(&out[2 * NPIX + p], acc2);
            atomicAdd(&out[3 * NPIX + p], acc3);
        }
        __syncthreads();   // all readers done with this buffer
    }
}

typedef CUresult (*EncodeFn)(
    CUtensorMap*, CUtensorMapDataType, cuuint32_t, void*,
    const cuuint64_t*, const cuuint64_t*, const cuuint32_t*, const cuuint32_t*,
    CUtensorMapInterleave, CUtensorMapSwizzle, CUtensorMapL2promotion,
    CUtensorMapFloatOOBfill);

extern "C" void kernel_launch(void* const* d_in, const int* in_sizes, int n_in,
                              void* d_out, int out_size)
{
    const float* sino = (const float*)d_in[0];  // (4,1,128,2048)
    const float* lut  = (const float*)d_in[1];  // (256,256,128,2)
    if (n_in >= 2 && in_sizes[0] > in_sizes[1]) {  // safety: sino is smaller
        const float* t = sino; sino = lut; lut = t;
    }
    float* out = (float*)d_out;

    // Encode LUT tensor map: 2D [256 floats/pixel, 65536 pixels],
    // box [8 floats, 256 pixels], no swizzle, NO L2 promotion (32B rows).
    EncodeFn encode = nullptr;
    cudaDriverEntryPointQueryResult qr;
    cudaGetDriverEntryPointByVersion("cuTensorMapEncodeTiled", (void**)&encode,
                                     12000, cudaEnableDefault, &qr);
    CUtensorMap tmap;
    cuuint64_t dims[2]    = {NDET * 2, NPIX};
    cuuint64_t strides[1] = {NDET * 2 * sizeof(float)};   // 1024 B
    cuuint32_t box[2]     = {8, 256};
    cuuint32_t estr[2]    = {1, 1};
    encode(&tmap, CU_TENSOR_MAP_DATA_TYPE_FLOAT32, 2, (void*)lut,
           dims, strides, box, estr,
           CU_TENSOR_MAP_INTERLEAVE_NONE, CU_TENSOR_MAP_SWIZZLE_NONE,
           CU_TENSOR_MAP_L2_PROMOTION_NONE, CU_TENSOR_MAP_FLOAT_OOB_FILL_NONE);

    cudaFuncSetAttribute(das_kernel,
                         cudaFuncAttributeMaxDynamicSharedMemorySize,
                         SMEM_TOTAL);

    // Output is poisoned; atomics need zeros.
    cudaMemsetAsync(d_out, 0, (size_t)out_size * sizeof(float), 0);

    dim3 grid(PTILES, GRIDY);
    das_kernel<<<grid, THREADS, SMEM_TOTAL>>>(tmap, sino, out);
}

// round 8
// speedup vs baseline: 1.3124x; 1.3124x over previous
#include <cuda_runtime.h>
#include <cuda_fp16.h>
#include <cuda.h>
#include <math.h>
#include <stdint.h>

// DelayAndSumLinear, round 7.
// R6 (TMA double-buffer) cut kernel time to 25.9us but stalled on mbar_wait:
// issue distance 1, stage fill latency > stage compute. Changes:
//  - 3-stage TMA ring (48KB), issue distance 3: stages 0..2 issued before the
//    sino fill; after consuming stage i, issue stage i+3. full-wait becomes
//    fast-path.
//  - everything else unchanged (DCH=4, PPP=512, 512thr, 2 blocks/SM, L2
//    promotion NONE, warp-coalesced REDG atomics).

#define NT      2048
#define NDET    128
#define NPIX    65536
#define NB      4
#define DCH     4
#define GRIDY   (NDET / DCH)         // 32
#define PTILES  9                    // 288 blocks = 1 wave @ 2/SM
#define THREADS 512
#define PPP     512                  // pixels per stage (2 TMA boxes of 256)
#define DEPTH   3
#define SMEM_ENTRIES (DCH * NT)      // sino: 8192 x uint2 = 64 KB

#define SINO_BYTES   (SMEM_ENTRIES * 8)          // 65536
#define STAGE_BYTES  (PPP * 32)                  // 16384
#define OFF_RING     SINO_BYTES                  // 65536
#define OFF_MBAR     (OFF_RING + DEPTH * STAGE_BYTES)   // 114688
#define SMEM_TOTAL   (OFF_MBAR + 64)

__device__ __forceinline__ uint32_t smem_u32(const void* p) {
    uint32_t a;
    asm("{ .reg .u64 t; cvta.to.shared.u64 t, %1; cvt.u32.u64 %0, t; }"
        : "=r"(a) : "l"(p));
    return a;
}
__device__ __forceinline__ void mbar_init(uint32_t m, uint32_t cnt) {
    asm volatile("mbarrier.init.shared.b64 [%0], %1;" :: "r"(m), "r"(cnt) : "memory");
}
__device__ __forceinline__ void mbar_expect(uint32_t m, uint32_t bytes) {
    asm volatile("mbarrier.arrive.expect_tx.shared.b64 _, [%0], %1;"
                 :: "r"(m), "r"(bytes) : "memory");
}
__device__ __forceinline__ void mbar_wait(uint32_t m, uint32_t parity) {
    asm volatile(
        "{\n\t.reg .pred P;\n\t"
        "W%=:\n\t"
        "mbarrier.try_wait.parity.acquire.cta.shared::cta.b64 P, [%0], %1, 0x989680;\n\t"
        "@P bra D%=;\n\t"
        "bra W%=;\n\t"
        "D%=:\n\t}"
        :: "r"(m), "r"(parity) : "memory");
}
__device__ __forceinline__ void tma_2d(uint32_t dst, const CUtensorMap* map,
                                       int x, int y, uint32_t mbar) {
    asm volatile(
        "cp.async.bulk.tensor.2d.shared::cta.global.tile.mbarrier::complete_tx::bytes "
        "[%0], [%1, {%2, %3}], [%4];"
        :: "r"(dst), "l"(map), "r"(x), "r"(y), "r"(mbar) : "memory");
}

__global__ __launch_bounds__(THREADS, 2)
void das_kernel(const __grid_constant__ CUtensorMap tmap,
                const float* __restrict__ sino,
                float* __restrict__ out)
{
    extern __shared__ char smem[];
    uint2* s2 = (uint2*)smem;                       // sino chunk
    const uint32_t sbase = smem_u32(smem);

    const int tid    = threadIdx.x;
    const int dbase  = blockIdx.y * DCH;
    const int xcoord = dbase * 2;                   // LUT dim0 element offset

    const int tileSize = (NPIX + PTILES - 1) / PTILES;  // 7282
    const int p0 = blockIdx.x * tileSize;
    const int p1 = min(p0 + tileSize, NPIX);
    const int nPass = (p1 - p0 + PPP - 1) / PPP;        // 15

    // ---- init mbarriers; issue stages 0..DEPTH-1 before the sino fill ----
    if (tid == 0) {
        #pragma unroll
        for (int s = 0; s < DEPTH; ++s) mbar_init(sbase + OFF_MBAR + 8 * s, 1);
    }
    __syncthreads();
    if (tid == 0) {
        #pragma unroll
        for (int s = 0; s < DEPTH; ++s) {
            uint32_t mb = sbase + OFF_MBAR + 8 * s;
            uint32_t db = sbase + OFF_RING + s * STAGE_BYTES;
            int      yb = p0 + s * PPP;
            mbar_expect(mb, STAGE_BYTES);
            tma_2d(db,        &tmap, xcoord, yb,       mb);
            tma_2d(db + 8192, &tmap, xcoord, yb + 256, mb);
        }
    }

    // ---- stage sino chunk: 4 dets x 2048 t x 4 batches as fp16 quads ----
    #pragma unroll
    for (int it = 0; it < SMEM_ENTRIES / THREADS; ++it) {
        int idx = it * THREADS + tid;
        int j   = idx >> 11;
        int t   = idx & (NT - 1);
        const float* sp = sino + (size_t)(dbase + j) * NT + t;
        float f0 = sp[0 * NDET * NT];
        float f1 = sp[1 * NDET * NT];
        float f2 = sp[2 * NDET * NT];
        float f3 = sp[3 * NDET * NT];
        half2 h01 = __floats2half2_rn(f0, f1);
        half2 h23 = __floats2half2_rn(f2, f3);
        uint2 v;
        v.x = *(unsigned*)&h01;
        v.y = *(unsigned*)&h23;
        s2[idx] = v;
    }

    // Hann apodization / norm folded per det (Hann sum over 128 pts = 63.5).
    float w[DCH];
    #pragma unroll
    for (int j = 0; j < DCH; ++j) {
        float d = (float)(dbase + j);
        w[j] = (0.5f - 0.5f * cosf(6.283185307179586f * d / 127.0f))
               * (1.0f / 63.5f);
    }

    __syncthreads();   // sino chunk ready

    for (int i = 0; i < nPass; ++i) {
        const int      slot = i % DEPTH;
        const uint32_t mb   = sbase + OFF_MBAR + 8 * slot;

        mbar_wait(mb, (i / DEPTH) & 1);

        int p = p0 + i * PPP + tid;
        if (p < p1) {
            const float4* lb =
                (const float4*)(smem + OFF_RING + slot * STAGE_BYTES);
            float4 A = lb[tid * 2];       // (tof0,a0,tof1,a1)
            float4 B = lb[tid * 2 + 1];   // (tof2,a2,tof3,a3)

            float tofs[DCH] = {A.x, A.z, B.x, B.z};
            float als [DCH] = {A.y, A.w, B.y, B.w};

            float acc0 = 0.f, acc1 = 0.f, acc2 = 0.f, acc3 = 0.f;
            #pragma unroll
            for (int j = 0; j < DCH; ++j) {
                float tof = tofs[j];
                float al  = als[j];
                float kf  = floorf(tof);
                int   k0  = (int)fminf(fmaxf(kf, 0.0f), (float)(NT - 2));
                float wv  = (kf >= 0.0f && kf <= (float)(NT - 2)) ? w[j] : 0.0f;

                uint2 e0 = s2[j * NT + k0];
                uint2 e1 = s2[j * NT + k0 + 1];
                float2 s0a = __half22float2(*(half2*)&e0.x);
                float2 s0b = __half22float2(*(half2*)&e0.y);
                float2 s1a = __half22float2(*(half2*)&e1.x);
                float2 s1b = __half22float2(*(half2*)&e1.y);

                float wa = wv * al;
                float wb = wv - wa;
                acc0 = fmaf(wb, s0a.x, fmaf(wa, s1a.x, acc0));
                acc1 = fmaf(wb, s0a.y, fmaf(wa, s1a.y, acc1));
                acc2 = fmaf(wb, s0b.x, fmaf(wa, s1b.x, acc2));
                acc3 = fmaf(wb, s0b.y, fmaf(wa, s1b.y, acc3));
            }

            atomicAdd(&out[0 * NPIX + p], acc0);   // warp-coalesced REDG
            atomicAdd(&out[1 * NPIX + p], acc1);
            atomicAdd(&out[2 * NPIX + p], acc2);
            atomicAdd(&out[3 * NPIX + p], acc3);
        }
        __syncthreads();   // all threads done with this slot

        // refill this slot with stage i+DEPTH
        if (tid == 0 && i + DEPTH < nPass) {
            uint32_t db = sbase + OFF_RING + slot * STAGE_BYTES;
            int      yb = p0 + (i + DEPTH) * PPP;
            mbar_expect(mb, STAGE_BYTES);
            tma_2d(db,        &tmap, xcoord, yb,       mb);
            tma_2d(db + 8192, &tmap, xcoord, yb + 256, mb);
        }
    }
}

typedef CUresult (*EncodeFn)(
    CUtensorMap*, CUtensorMapDataType, cuuint32_t, void*,
    const cuuint64_t*, const cuuint64_t*, const cuuint32_t*, const cuuint32_t*,
    CUtensorMapInterleave, CUtensorMapSwizzle, CUtensorMapL2promotion,
    CUtensorMapFloatOOBfill);

extern "C" void kernel_launch(void* const* d_in, const int* in_sizes, int n_in,
                              void* d_out, int out_size)
{
    const float* sino = (const float*)d_in[0];  // (4,1,128,2048)
    const float* lut  = (const float*)d_in[1];  // (256,256,128,2)
    if (n_in >= 2 && in_sizes[0] > in_sizes[1]) {  // safety: sino is smaller
        const float* t = sino; sino = lut; lut = t;
    }
    float* out = (float*)d_out;

    // LUT tensor map: 2D [256 floats/pixel, 65536 pixels], box [8 x 256],
    // no swizzle, NO L2 promotion (32B rows; avoid DRAM overfetch).
    EncodeFn encode = nullptr;
    cudaDriverEntryPointQueryResult qr;
    cudaGetDriverEntryPointByVersion("cuTensorMapEncodeTiled", (void**)&encode,
                                     12000, cudaEnableDefault, &qr);
    CUtensorMap tmap;
    cuuint64_t dims[2]    = {NDET * 2, NPIX};
    cuuint64_t strides[1] = {NDET * 2 * sizeof(float)};   // 1024 B
    cuuint32_t box[2]     = {8, 256};
    cuuint32_t estr[2]    = {1, 1};
    encode(&tmap, CU_TENSOR_MAP_DATA_TYPE_FLOAT32, 2, (void*)lut,
           dims, strides, box, estr,
           CU_TENSOR_MAP_INTERLEAVE_NONE, CU_TENSOR_MAP_SWIZZLE_NONE,
           CU_TENSOR_MAP_L2_PROMOTION_NONE, CU_TENSOR_MAP_FLOAT_OOB_FILL_NONE);

    cudaFuncSetAttribute(das_kernel,
                         cudaFuncAttributeMaxDynamicSharedMemorySize,
                         SMEM_TOTAL);

    // Output is poisoned; atomics need zeros.
    cudaMemsetAsync(d_out, 0, (size_t)out_size * sizeof(float), 0);

    dim3 grid(PTILES, GRIDY);
    das_kernel<<<grid, THREADS, SMEM_TOTAL>>>(tmap, sino, out);
}